// round 8
// baseline (speedup 1.0000x reference)
#include <cuda_runtime.h>
#include <cuda_bf16.h>
#include <cstdint>
#include <math.h>

#define BATCH 128
#define TT    127
#define SS    128
#define DIN   48
#define DKD   128
#define HH    8
#define LL    6
#define PP    8128
#define LHN   48
#define BS    (BATCH*SS)     /* 16384 */
#define BSD   (BS*DKD)       /* 2097152 */

typedef __nv_bfloat16 bf16;

// ---------------- scratch ----------------------------------------------------
__device__ float g_h[BSD];
__device__ float g_nrm[BS];
__device__ float g_cosv[LHN*PP];
__device__ float g_sinv[LHN*PP];
__device__ bf16  g_uhi[BSD],  g_ulo[BSD];
__device__ bf16  g_Wthi[LHN*DKD*DKD], g_Wtlo[LHN*DKD*DKD];
__device__ bf16  g_Vwhi[LHN*DKD*DKD], g_Vwlo[LHN*DKD*DKD];

// ---------------- helpers -----------------------------------------------------
__device__ __forceinline__ uint32_t smem_u32(const void* p) {
    uint32_t a;
    asm("{ .reg .u64 t; cvta.to.shared.u64 t, %1; cvt.u32.u64 %0, t; }" : "=r"(a) : "l"(p));
    return a;
}
__device__ __forceinline__ void split2(float x, bf16& h, bf16& l)
{
    h = __float2bfloat16_rn(x);
    l = __float2bfloat16_rn(x - __bfloat162float(h));
}
__device__ __forceinline__ void split_pack2(float x, float y, uint32_t& hi, uint32_t& lo)
{
    bf16 hx, lx, hy, ly;
    split2(x, hx, lx); split2(y, hy, ly);
    __nv_bfloat162 H = __halves2bfloat162(hx, hy);
    __nv_bfloat162 L = __halves2bfloat162(lx, ly);
    hi = *reinterpret_cast<uint32_t*>(&H);
    lo = *reinterpret_cast<uint32_t*>(&L);
}
__device__ __forceinline__ void ldmx4(uint32_t* r, uint32_t addr)
{
    asm volatile("ldmatrix.sync.aligned.m8n8.x4.shared.b16 {%0,%1,%2,%3}, [%4];"
        : "=r"(r[0]), "=r"(r[1]), "=r"(r[2]), "=r"(r[3]) : "r"(addr));
}
__device__ __forceinline__ void mma16816(float* d, const uint32_t* a, const uint32_t* b)
{
    asm volatile("mma.sync.aligned.m16n8k16.row.col.f32.bf16.bf16.f32 "
        "{%0,%1,%2,%3}, {%4,%5,%6,%7}, {%8,%9}, {%0,%1,%2,%3};"
        : "+f"(d[0]), "+f"(d[1]), "+f"(d[2]), "+f"(d[3])
        : "r"(a[0]), "r"(a[1]), "r"(a[2]), "r"(a[3]), "r"(b[0]), "r"(b[1]));
}
#define CP16(dst, src) \
    asm volatile("cp.async.cg.shared.global [%0], [%1], 16;" :: "r"(dst), "l"(src))
#define CP_COMMIT() asm volatile("cp.async.commit_group;" ::: "memory")
#define CP_WAIT0()  asm volatile("cp.async.wait_group 0;" ::: "memory")
#define CP_WAIT1()  asm volatile("cp.async.wait_group 1;" ::: "memory")

// ---------------- embed + class token + LN0 ---------------------------------
__global__ void k_embed(const float* __restrict__ x, const float* __restrict__ ew,
                        const float* __restrict__ eb, const float* __restrict__ ct,
                        const float* __restrict__ g0, const float* __restrict__ b0)
{
    int bx = blockIdx.x;
    int b = bx >> 7, s = bx & 127;
    int d = threadIdx.x;
    __shared__ float xs[DIN];
    __shared__ float red[8];
    float v;
    if (s == 0) {
        v = ct[d];
    } else {
        if (d < DIN) xs[d] = x[(b*TT + (s-1))*DIN + d];
        __syncthreads();
        float acc = eb[d];
        const float* wrow = ew + d*DIN;
#pragma unroll
        for (int f = 0; f < DIN; f++) acc += xs[f]*wrow[f];
        v = acc;
    }
    float sum = v, sq = v*v;
#pragma unroll
    for (int o = 16; o; o >>= 1) {
        sum += __shfl_xor_sync(0xffffffffu, sum, o);
        sq  += __shfl_xor_sync(0xffffffffu, sq,  o);
    }
    if ((d & 31) == 0) { red[d>>5] = sum; red[4 + (d>>5)] = sq; }
    __syncthreads();
    float ts = red[0]+red[1]+red[2]+red[3];
    float tq = red[4]+red[5]+red[6]+red[7];
    float mean = ts * (1.0f/DKD);
    float var  = tq * (1.0f/DKD) - mean*mean;
    float inv  = rsqrtf(var + 1e-5f);
    g_h[(size_t)bx*DKD + d] = (v - mean)*inv*g0[d] + b0[d];
}

// ---------------- sincos precompute ------------------------------------------
__global__ void k_cs(const float* __restrict__ phi)
{
    int i = blockIdx.x*blockDim.x + threadIdx.x;
    if (i < LHN*PP) {
        float s, c;
        sincosf(phi[i], &s, &c);
        g_cosv[i] = c; g_sinv[i] = s;
    }
}

// ---------------- split Vw ----------------------------------------------------
__global__ void k_splitVw(const float* __restrict__ Vw)
{
    int i = blockIdx.x*blockDim.x + threadIdx.x;
    if (i < LHN*DKD*DKD) {
        bf16 h, l; split2(Vw[i], h, l);
        g_Vwhi[i] = h; g_Vwlo[i] = l;
    }
}

// ---------------- W build: brick-wall Givens pyramid -> transposed splits ----
__global__ __launch_bounds__(256) void k_wbuild()
{
    int lh = blockIdx.x, cg = blockIdx.y;      // 48 x 4
    __shared__ float Wsh[SS][33];
    int tid = threadIdx.x;
    int col = tid & 31, slot = tid >> 5;
    for (int idx = tid; idx < SS*32; idx += 256) {
        int r = idx >> 5, c = idx & 31;
        Wsh[r][c] = (r == cg*32 + c) ? 1.0f : 0.0f;
    }
    __syncthreads();
    const float* cb = g_cosv + lh*PP;
    const float* sb = g_sinv + lh*PP;
    for (int t = 0; t <= 2*(SS-2); t++) {
        int par  = t & 1;
        int imax = min(t, 2*(SS-2) - t);
        int cnt  = ((imax - par) >> 1) + 1;
        for (int r = slot; r < cnt; r += 8) {
            int i = par + 2*r;
            int k = (t + i) >> 1;
            int p = ((k*(k+1)) >> 1) + k - i;
            float c = cb[p], s = sb[p];
            float ra = Wsh[i][col], rb = Wsh[i+1][col];
            Wsh[i][col]   = c*ra - s*rb;
            Wsh[i+1][col] = s*ra + c*rb;
        }
        __syncthreads();
    }
    for (int idx = tid; idx < 32*SS; idx += 256) {
        int r = idx & 127, c = idx >> 7;
        float v = Wsh[r][c];
        bf16 hi, lo; split2(v, hi, lo);
        size_t o = (size_t)lh*DKD*DKD + (size_t)(cg*32 + c)*DKD + r;
        g_Wthi[o] = hi; g_Wtlo[o] = lo;
    }
}

// ---------------- token norms + u splits (layer-0 prep) -----------------------
__global__ void k_norm()
{
    int row = blockIdx.x;
    int d = threadIdx.x;
    float v = g_h[(size_t)row*DKD + d];
    float sq = v*v;
#pragma unroll
    for (int o = 16; o; o >>= 1) sq += __shfl_xor_sync(0xffffffffu, sq, o);
    __shared__ float red[4];
    if ((d & 31) == 0) red[d>>5] = sq;
    __syncthreads();
    float nrm = sqrtf(red[0]+red[1]+red[2]+red[3]);
    float u = v / nrm;
    size_t o = (size_t)row*DKD + d;
    bf16 hi, lo;
    split2(u, hi, lo); g_uhi[o] = hi; g_ulo[o] = lo;
    if (d == 0) g_nrm[row] = nrm;
}

// ---------------- persistent mega kernel --------------------------------------
#define TSTRIDE 136
#define TILE1   (128*TSTRIDE*2)        /* 34816 bytes, one bf16 tile */
#define RPAIR   (2*TILE1)              /* 69632: hi+lo pair */
#define R1O     0                      /* A: u (persistent) */
#define R2O     RPAIR                  /* Rv: W -> T1 -> P  */
#define R3O     (2*RPAIR)              /* Rt: Vw -> V^T     */
#define SMO_F   (3*RPAIR)
#define SMEM_TOTAL (3*RPAIR + 6656)

__device__ __forceinline__ void load_pair_async(uint32_t dst,
    const bf16* __restrict__ hi, const bf16* __restrict__ lo, int tid)
{
#pragma unroll
    for (int it = 0; it < 8; it++) {
        int idx = it*256 + tid;
        int row = idx >> 4, chunk = idx & 15;
        uint32_t so = dst + (row*TSTRIDE + chunk*8)*2;
        CP16(so,         hi + row*DKD + chunk*8);
        CP16(so + TILE1, lo + row*DKD + chunk*8);
    }
}

// 2x4-split 3-term (hi*hi + lo*hi + hi*lo) 128x128x128 gemm
__device__ __forceinline__ void gemm3(uint32_t aBase, uint32_t bBase,
                                      float acc[4][4][4], int lane, int wm, int wn)
{
    uint32_t aoff[4], b4off[2];
#pragma unroll
    for (int mi = 0; mi < 4; mi++)
        aoff[mi] = aBase + ((wm*64 + mi*16 + (lane & 15))*TSTRIDE + (lane >> 4)*8) * 2;
#pragma unroll
    for (int njp = 0; njp < 2; njp++)
        b4off[njp] = bBase + ((wn*32 + njp*16 + ((lane>>4)*8) + (lane & 7))*TSTRIDE
                              + (((lane >> 3) & 1)*8)) * 2;
#pragma unroll
    for (int mi = 0; mi < 4; mi++)
#pragma unroll
        for (int nj = 0; nj < 4; nj++)
#pragma unroll
            for (int q = 0; q < 4; q++) acc[mi][nj][q] = 0.0f;

#pragma unroll 2
    for (int kk = 0; kk < 8; kk++) {
        uint32_t k2 = kk*32;
        uint32_t ah[4][4], al[4][4], bh[2][4], bl[2][4];
#pragma unroll
        for (int mi = 0; mi < 4; mi++) {
            ldmx4(ah[mi], aoff[mi] + k2);
            ldmx4(al[mi], aoff[mi] + TILE1 + k2);
        }
#pragma unroll
        for (int njp = 0; njp < 2; njp++) {
            ldmx4(bh[njp], b4off[njp] + k2);
            ldmx4(bl[njp], b4off[njp] + TILE1 + k2);
        }
#pragma unroll
        for (int mi = 0; mi < 4; mi++)
#pragma unroll
            for (int nj = 0; nj < 4; nj++) {
                const uint32_t* bhp = &bh[nj>>1][(nj&1)*2];
                const uint32_t* blp = &bl[nj>>1][(nj&1)*2];
                mma16816(acc[mi][nj], ah[mi], bhp);
                mma16816(acc[mi][nj], al[mi], bhp);
                mma16816(acc[mi][nj], ah[mi], blp);
            }
    }
}

// accumulator fragments -> smem bf16 hi/lo tile (row-major A layout)
__device__ __forceinline__ void fragToTile(char* sm, uint32_t rOff, float acc[4][4][4],
                                           int lane, int wm, int wn)
{
    int gid = lane >> 2, tig = lane & 3;
#pragma unroll
    for (int mi = 0; mi < 4; mi++) {
        int r0 = wm*64 + mi*16 + gid;
#pragma unroll
        for (int nj = 0; nj < 4; nj++) {
            int c0 = wn*32 + nj*8 + tig*2;
#pragma unroll
            for (int half = 0; half < 2; half++) {
                int r = r0 + half*8;
                uint32_t hi, lo;
                split_pack2(acc[mi][nj][half*2], acc[mi][nj][half*2+1], hi, lo);
                *(uint32_t*)(sm + rOff + (r*TSTRIDE + c0)*2)         = hi;
                *(uint32_t*)(sm + rOff + TILE1 + (r*TSTRIDE + c0)*2) = lo;
            }
        }
    }
}

__global__ void __launch_bounds__(256, 1) k_mega(
    const float* __restrict__ Vb, const float* __restrict__ lng,
    const float* __restrict__ lnb, const float* __restrict__ mw,
    const float* __restrict__ mb, float* __restrict__ out)
{
    extern __shared__ char sm[];
    uint32_t smb = smem_u32(sm);

    int bx = blockIdx.x;                 // batch tile (one image)
    int tid = threadIdx.x, lane = tid & 31, wid = tid >> 5;
    int wm = wid >> 2, wn = wid & 3;
    int gid = lane >> 2, tig = lane & 3;

    float* fnrm = (float*)(sm + SMO_F);
    float* fvb  = fnrm + 128;
    float* fg   = fnrm + 256;
    float* fb   = fnrm + 384;
    float* red1 = fnrm + 512;            // 512 floats
    float* red2 = fnrm + 1024;           // 512 floats

    size_t tokBase = (size_t)bx*128*DKD;

    // prologue: u -> A (+W0), then Vw0 as second group
    load_pair_async(smb + R1O, g_uhi + tokBase, g_ulo + tokBase, tid);
    load_pair_async(smb + R2O, g_Wthi, g_Wtlo, tid);
    CP_COMMIT();
    load_pair_async(smb + R3O, g_Vwhi, g_Vwlo, tid);
    CP_COMMIT();
    if (tid < 128) fnrm[tid] = g_nrm[bx*128 + tid];

    float acc[4][4][4];
    float hsum[4][4][4];

    for (int l = 0; l < LL; l++) {
        float mbv = __ldg(mb + l);
#pragma unroll
        for (int mi = 0; mi < 4; mi++)
#pragma unroll
            for (int nj = 0; nj < 4; nj++)
#pragma unroll
                for (int q = 0; q < 4; q++) hsum[mi][nj][q] = 0.0f;

#pragma unroll 1
        for (int h = 0; h < HH; h++) {
            int lh = l*HH + h;
            if (tid < 128) {
                fvb[tid] = Vb[lh*DKD + tid];
                fg[tid]  = lng[(size_t)lh*DKD + tid];
                fb[tid]  = lnb[(size_t)lh*DKD + tid];
            }
            CP_WAIT1();                    // W (older group) ready; Vw may fly
            __syncthreads();               // S1: W + params (+A updates) visible

            // GEMM1: T1 = u @ W  (A, Rv)
            gemm3(smb + R1O, smb + R2O, acc, lane, wm, wn);
            __syncthreads();               // S2: W consumed
            fragToTile(sm, R2O, acc, lane, wm, wn);   // T1 -> Rv
            __syncthreads();               // S3

            // GEMM2: M = T1 @ u^T  (Rv, A)
            gemm3(smb + R2O, smb + R1O, acc, lane, wm, wn);
            __syncthreads();               // S4: T1 consumed

            // register softmax (A = M^2*n*n*scale >= 0, no max pass)
            {
                const float scale = 0.08838834764831845f;    // 1/sqrt(128)
                float nc[8];
#pragma unroll
                for (int nj = 0; nj < 4; nj++) {
                    int c0 = wn*32 + nj*8 + tig*2;
                    nc[2*nj]   = fnrm[c0];
                    nc[2*nj+1] = fnrm[c0+1];
                }
#pragma unroll
                for (int mi = 0; mi < 4; mi++)
#pragma unroll
                for (int half = 0; half < 2; half++) {
                    int r = wm*64 + mi*16 + half*8 + gid;
                    float nr = fnrm[r] * scale;
                    float s = 0.0f;
#pragma unroll
                    for (int nj = 0; nj < 4; nj++) {
                        float m0 = acc[mi][nj][half*2], m1 = acc[mi][nj][half*2+1];
                        float e0 = __expf(m0*m0 * nr * nc[2*nj]);
                        float e1 = __expf(m1*m1 * nr * nc[2*nj+1]);
                        acc[mi][nj][half*2]   = e0;
                        acc[mi][nj][half*2+1] = e1;
                        s += e0 + e1;
                    }
                    s += __shfl_xor_sync(0xffffffffu, s, 1);
                    s += __shfl_xor_sync(0xffffffffu, s, 2);
                    if (tig == 0) red1[r*4 + wn] = s;
                }
                __syncthreads();           // S5: partial sums
#pragma unroll
                for (int mi = 0; mi < 4; mi++)
#pragma unroll
                for (int half = 0; half < 2; half++) {
                    int r = wm*64 + mi*16 + half*8 + gid;
                    float inv = 1.0f / (red1[r*4] + red1[r*4+1] + red1[r*4+2] + red1[r*4+3]);
#pragma unroll
                    for (int nj = 0; nj < 4; nj++) {
                        int c0 = wn*32 + nj*8 + tig*2;
                        uint32_t hi, lo;
                        split_pack2(acc[mi][nj][half*2]*inv, acc[mi][nj][half*2+1]*inv, hi, lo);
                        *(uint32_t*)(sm + R2O + (r*TSTRIDE + c0)*2)         = hi;
                        *(uint32_t*)(sm + R2O + TILE1 + (r*TSTRIDE + c0)*2) = lo;
                    }
                }
            }
            CP_WAIT0();                    // Vw ready
            __syncthreads();               // S6: P visible, Vw visible

            // GEMM3: V' = u @ Vw^T  (A, Rt); V = V'*nrm[s] + vb
            gemm3(smb + R1O, smb + R3O, acc, lane, wm, wn);
            __syncthreads();               // S7: Vw consumed

            // scatter V^T -> Rt
#pragma unroll
            for (int mi = 0; mi < 4; mi++) {
                int s0 = wm*64 + mi*16 + gid;
#pragma unroll
                for (int nj = 0; nj < 4; nj++) {
                    int e0 = wn*32 + nj*8 + tig*2;
                    float vb0 = fvb[e0], vb1 = fvb[e0+1];
#pragma unroll
                    for (int half = 0; half < 2; half++) {
                        int ss = s0 + half*8;
                        float ns = fnrm[ss];
                        float v0 = acc[mi][nj][half*2]*ns   + vb0;
                        float v1 = acc[mi][nj][half*2+1]*ns + vb1;
                        bf16 h0, l0, h1, l1;
                        split2(v0, h0, l0); split2(v1, h1, l1);
                        *(bf16*)(sm + R3O + (e0*TSTRIDE + ss)*2)             = h0;
                        *(bf16*)(sm + R3O + TILE1 + (e0*TSTRIDE + ss)*2)     = l0;
                        *(bf16*)(sm + R3O + ((e0+1)*TSTRIDE + ss)*2)         = h1;
                        *(bf16*)(sm + R3O + TILE1 + ((e0+1)*TSTRIDE + ss)*2) = l1;
                    }
                }
            }
            __syncthreads();               // S8: V^T staged

            // GEMM4: O = P @ V^T  (Rv, Rt)
            gemm3(smb + R2O, smb + R3O, acc, lane, wm, wn);
            __syncthreads();               // S9: Rv/Rt free

            // prefetch next head's W and Vw (separate groups)
            if (lh + 1 < LHN) {
                size_t no = (size_t)(lh+1)*DKD*DKD;
                load_pair_async(smb + R2O, g_Wthi + no, g_Wtlo + no, tid);
                CP_COMMIT();
                load_pair_async(smb + R3O, g_Vwhi + no, g_Vwlo + no, tid);
                CP_COMMIT();
            }

            // epilogue: resid from u-tile, LN, accumulate into hsum
            {
                float mwv = __ldg(mw + lh);
#pragma unroll
                for (int mi = 0; mi < 4; mi++)
#pragma unroll
                for (int half = 0; half < 2; half++) {
                    int r = wm*64 + mi*16 + half*8 + gid;
                    float nr = fnrm[r];
                    float s = 0.0f, s2 = 0.0f;
#pragma unroll
                    for (int nj = 0; nj < 4; nj++) {
                        int c0 = wn*32 + nj*8 + tig*2;
                        __nv_bfloat162 uh = *(__nv_bfloat162*)(sm + R1O + (r*TSTRIDE + c0)*2);
                        __nv_bfloat162 ul = *(__nv_bfloat162*)(sm + R1O + TILE1 + (r*TSTRIDE + c0)*2);
                        float r0 = (__bfloat162float(uh.x) + __bfloat162float(ul.x)) * nr;
                        float r1 = (__bfloat162float(uh.y) + __bfloat162float(ul.y)) * nr;
                        float v0 = acc[mi][nj][half*2]   + r0;
                        float v1 = acc[mi][nj][half*2+1] + r1;
                        acc[mi][nj][half*2]   = v0;
                        acc[mi][nj][half*2+1] = v1;
                        s  += v0 + v1;
                        s2 += v0*v0 + v1*v1;
                    }
                    s  += __shfl_xor_sync(0xffffffffu, s, 1);
                    s  += __shfl_xor_sync(0xffffffffu, s, 2);
                    s2 += __shfl_xor_sync(0xffffffffu, s2, 1);
                    s2 += __shfl_xor_sync(0xffffffffu, s2, 2);
                    if (tig == 0) { red1[r*4 + wn] = s; red2[r*4 + wn] = s2; }
                }
                __syncthreads();           // S10
#pragma unroll
                for (int mi = 0; mi < 4; mi++)
#pragma unroll
                for (int half = 0; half < 2; half++) {
                    int r = wm*64 + mi*16 + half*8 + gid;
                    float s  = red1[r*4] + red1[r*4+1] + red1[r*4+2] + red1[r*4+3];
                    float s2 = red2[r*4] + red2[r*4+1] + red2[r*4+2] + red2[r*4+3];
                    float mean = s * (1.0f/DKD);
                    float var  = s2 * (1.0f/DKD) - mean*mean;
                    float inv  = rsqrtf(var + 1e-5f);
#pragma unroll
                    for (int nj = 0; nj < 4; nj++) {
                        int c0 = wn*32 + nj*8 + tig*2;
                        hsum[mi][nj][half*2]   += ((acc[mi][nj][half*2]  -mean)*inv*fg[c0]   + fb[c0]  ) * mwv;
                        hsum[mi][nj][half*2+1] += ((acc[mi][nj][half*2+1]-mean)*inv*fg[c0+1] + fb[c0+1]) * mwv;
                    }
                }
                __syncthreads();           // S11: red/params free for next head
            }
        } // heads

        // ---- layer end: merged = hsum + mb[l] ----
        if (l < LL-1) {
            // row sum-of-squares of merged
#pragma unroll
            for (int mi = 0; mi < 4; mi++)
#pragma unroll
            for (int half = 0; half < 2; half++) {
                int r = wm*64 + mi*16 + half*8 + gid;
                float s2 = 0.0f;
#pragma unroll
                for (int nj = 0; nj < 4; nj++) {
                    float m0 = hsum[mi][nj][half*2]   + mbv;
                    float m1 = hsum[mi][nj][half*2+1] + mbv;
                    s2 += m0*m0 + m1*m1;
                }
                s2 += __shfl_xor_sync(0xffffffffu, s2, 1);
                s2 += __shfl_xor_sync(0xffffffffu, s2, 2);
                if (tig == 0) red1[r*4 + wn] = s2;
            }
            __syncthreads();
            // write new u splits into A, update fnrm
#pragma unroll
            for (int mi = 0; mi < 4; mi++)
#pragma unroll
            for (int half = 0; half < 2; half++) {
                int r = wm*64 + mi*16 + half*8 + gid;
                float nrm = sqrtf(red1[r*4] + red1[r*4+1] + red1[r*4+2] + red1[r*4+3]);
                float inv = 1.0f / nrm;
#pragma unroll
                for (int nj = 0; nj < 4; nj++) {
                    int c0 = wn*32 + nj*8 + tig*2;
                    uint32_t hi, lo;
                    split_pack2((hsum[mi][nj][half*2] + mbv)*inv,
                                (hsum[mi][nj][half*2+1] + mbv)*inv, hi, lo);
                    *(uint32_t*)(sm + R1O + (r*TSTRIDE + c0)*2)         = hi;
                    *(uint32_t*)(sm + R1O + TILE1 + (r*TSTRIDE + c0)*2) = lo;
                }
                if (wn == 0 && tig == 0) fnrm[r] = nrm;
            }
            // visibility covered by S1 sync of next head
        } else {
            // final output: token row 127 of this image
#pragma unroll
            for (int mi = 0; mi < 4; mi++)
#pragma unroll
            for (int half = 0; half < 2; half++) {
                int r = wm*64 + mi*16 + half*8 + gid;
                if (r == 127) {
#pragma unroll
                    for (int nj = 0; nj < 4; nj++) {
                        int c0 = wn*32 + nj*8 + tig*2;
                        float2 o;
                        o.x = hsum[mi][nj][half*2]   + mbv;
                        o.y = hsum[mi][nj][half*2+1] + mbv;
                        *(float2*)(out + bx*DKD + c0) = o;
                    }
                }
            }
        }
    } // layers
}

// ---------------- launch ------------------------------------------------------
extern "C" void kernel_launch(void* const* d_in, const int* in_sizes, int n_in,
                              void* d_out, int out_size)
{
    const float* x        = (const float*)d_in[0];
    const float* embed_w  = (const float*)d_in[1];
    const float* embed_b  = (const float*)d_in[2];
    const float* class_tk = (const float*)d_in[3];
    const float* norm0_g  = (const float*)d_in[4];
    const float* norm0_b  = (const float*)d_in[5];
    const float* Vw       = (const float*)d_in[6];
    const float* Vb       = (const float*)d_in[7];
    const float* ln_g     = (const float*)d_in[8];
    const float* ln_b     = (const float*)d_in[9];
    const float* phi      = (const float*)d_in[10];
    const float* merger_w = (const float*)d_in[11];
    const float* merger_b = (const float*)d_in[12];
    float* out = (float*)d_out;

    static int smem_set = 0;
    if (!smem_set) {
        cudaFuncSetAttribute(k_mega, cudaFuncAttributeMaxDynamicSharedMemorySize, SMEM_TOTAL);
        smem_set = 1;
    }

    k_embed<<<BS, 128>>>(x, embed_w, embed_b, class_tk, norm0_g, norm0_b);
    k_cs<<<(LHN*PP + 255)/256, 256>>>(phi);
    k_wbuild<<<dim3(LHN, 4), 256>>>();
    k_splitVw<<<(LHN*DKD*DKD + 255)/256, 256>>>(Vw);
    k_norm<<<BS, 128>>>();
    k_mega<<<BATCH, 256, SMEM_TOTAL>>>(Vb, ln_g, ln_b, merger_w, merger_b, out);
}

// round 9
// speedup vs baseline: 1.7578x; 1.7578x over previous
#include <cuda_runtime.h>
#include <cuda_fp16.h>
#include <cstdint>
#include <math.h>

#define BATCH 128
#define TT    127
#define SS    128
#define DIN   48
#define DKD   128
#define HH    8
#define LL    6
#define PP    8128
#define LHN   48
#define BS    (BATCH*SS)     /* 16384 */
#define BSD   (BS*DKD)       /* 2097152 */

typedef __half fp16;

// ---------------- scratch ----------------------------------------------------
__device__ float g_h[BSD];
__device__ float g_nrm[BS];
__device__ float g_cosv[LHN*PP];
__device__ float g_sinv[LHN*PP];
__device__ fp16  g_uhi[BSD],  g_ulo[BSD];
__device__ fp16  g_hhi[BSD],  g_hlo[BSD];
__device__ fp16  g_Wthi[LHN*DKD*DKD];            /* B-side: hi only */
__device__ fp16  g_Vwhi[LHN*DKD*DKD];            /* B-side: hi only */
__device__ float g_hs[(size_t)HH*BSD];

// ---------------- helpers -----------------------------------------------------
__device__ __forceinline__ uint32_t smem_u32(const void* p) {
    uint32_t a;
    asm("{ .reg .u64 t; cvta.to.shared.u64 t, %1; cvt.u32.u64 %0, t; }" : "=r"(a) : "l"(p));
    return a;
}
__device__ __forceinline__ void split2(float x, fp16& h, fp16& l)
{
    h = __float2half_rn(x);
    l = __float2half_rn(x - __half2float(h));
}
__device__ __forceinline__ void split_pack2(float x, float y, uint32_t& hi, uint32_t& lo)
{
    fp16 hx, lx, hy, ly;
    split2(x, hx, lx); split2(y, hy, ly);
    __half2 H = __halves2half2(hx, hy);
    __half2 L = __halves2half2(lx, ly);
    hi = *reinterpret_cast<uint32_t*>(&H);
    lo = *reinterpret_cast<uint32_t*>(&L);
}
__device__ __forceinline__ void ldmx4(uint32_t* r, uint32_t addr)
{
    asm volatile("ldmatrix.sync.aligned.m8n8.x4.shared.b16 {%0,%1,%2,%3}, [%4];"
        : "=r"(r[0]), "=r"(r[1]), "=r"(r[2]), "=r"(r[3]) : "r"(addr));
}
__device__ __forceinline__ void mma16816(float* d, const uint32_t* a, const uint32_t* b)
{
    asm volatile("mma.sync.aligned.m16n8k16.row.col.f32.f16.f16.f32 "
        "{%0,%1,%2,%3}, {%4,%5,%6,%7}, {%8,%9}, {%0,%1,%2,%3};"
        : "+f"(d[0]), "+f"(d[1]), "+f"(d[2]), "+f"(d[3])
        : "r"(a[0]), "r"(a[1]), "r"(a[2]), "r"(a[3]), "r"(b[0]), "r"(b[1]));
}
#define CP16(dst, src) \
    asm volatile("cp.async.cg.shared.global [%0], [%1], 16;" :: "r"(dst), "l"(src))
#define CP_COMMIT() asm volatile("cp.async.commit_group;" ::: "memory")
#define CP_WAIT0()  asm volatile("cp.async.wait_group 0;" ::: "memory")

// ---------------- embed + class token + LN0 ---------------------------------
__global__ void k_embed(const float* __restrict__ x, const float* __restrict__ ew,
                        const float* __restrict__ eb, const float* __restrict__ ct,
                        const float* __restrict__ g0, const float* __restrict__ b0)
{
    int bx = blockIdx.x;
    int b = bx >> 7, s = bx & 127;
    int d = threadIdx.x;
    __shared__ float xs[DIN];
    __shared__ float red[8];
    float v;
    if (s == 0) {
        v = ct[d];
    } else {
        if (d < DIN) xs[d] = x[(b*TT + (s-1))*DIN + d];
        __syncthreads();
        float acc = eb[d];
        const float* wrow = ew + d*DIN;
#pragma unroll
        for (int f = 0; f < DIN; f++) acc += xs[f]*wrow[f];
        v = acc;
    }
    float sum = v, sq = v*v;
#pragma unroll
    for (int o = 16; o; o >>= 1) {
        sum += __shfl_xor_sync(0xffffffffu, sum, o);
        sq  += __shfl_xor_sync(0xffffffffu, sq,  o);
    }
    if ((d & 31) == 0) { red[d>>5] = sum; red[4 + (d>>5)] = sq; }
    __syncthreads();
    float ts = red[0]+red[1]+red[2]+red[3];
    float tq = red[4]+red[5]+red[6]+red[7];
    float mean = ts * (1.0f/DKD);
    float var  = tq * (1.0f/DKD) - mean*mean;
    float inv  = rsqrtf(var + 1e-5f);
    g_h[(size_t)bx*DKD + d] = (v - mean)*inv*g0[d] + b0[d];
}

// ---------------- sincos precompute ------------------------------------------
__global__ void k_cs(const float* __restrict__ phi)
{
    int i = blockIdx.x*blockDim.x + threadIdx.x;
    if (i < LHN*PP) {
        float s, c;
        sincosf(phi[i], &s, &c);
        g_cosv[i] = c; g_sinv[i] = s;
    }
}

// ---------------- convert Vw (hi only) ----------------------------------------
__global__ void k_cvtVw(const float* __restrict__ Vw)
{
    int i = blockIdx.x*blockDim.x + threadIdx.x;
    if (i < LHN*DKD*DKD) g_Vwhi[i] = __float2half_rn(Vw[i]);
}

// ---------------- W build: brick-wall Givens pyramid -> transposed hi ---------
__global__ __launch_bounds__(256) void k_wbuild()
{
    int lh = blockIdx.x, cg = blockIdx.y;      // 48 x 4
    __shared__ float Wsh[SS][33];
    int tid = threadIdx.x;
    int col = tid & 31, slot = tid >> 5;
    for (int idx = tid; idx < SS*32; idx += 256) {
        int r = idx >> 5, c = idx & 31;
        Wsh[r][c] = (r == cg*32 + c) ? 1.0f : 0.0f;
    }
    __syncthreads();
    const float* cb = g_cosv + lh*PP;
    const float* sb = g_sinv + lh*PP;
    for (int t = 0; t <= 2*(SS-2); t++) {
        int par  = t & 1;
        int imax = min(t, 2*(SS-2) - t);
        int cnt  = ((imax - par) >> 1) + 1;
        for (int r = slot; r < cnt; r += 8) {
            int i = par + 2*r;
            int k = (t + i) >> 1;
            int p = ((k*(k+1)) >> 1) + k - i;
            float c = cb[p], s = sb[p];
            float ra = Wsh[i][col], rb = Wsh[i+1][col];
            Wsh[i][col]   = c*ra - s*rb;
            Wsh[i+1][col] = s*ra + c*rb;
        }
        __syncthreads();
    }
    for (int idx = tid; idx < 32*SS; idx += 256) {
        int r = idx & 127, c = idx >> 7;
        size_t o = (size_t)lh*DKD*DKD + (size_t)(cg*32 + c)*DKD + r;
        g_Wthi[o] = __float2half_rn(Wsh[r][c]);
    }
}

// ---------------- token norms + splits (layer-0 prep) -------------------------
__global__ void k_norm()
{
    int row = blockIdx.x;
    int d = threadIdx.x;
    float v = g_h[(size_t)row*DKD + d];
    float sq = v*v;
#pragma unroll
    for (int o = 16; o; o >>= 1) sq += __shfl_xor_sync(0xffffffffu, sq, o);
    __shared__ float red[4];
    if ((d & 31) == 0) red[d>>5] = sq;
    __syncthreads();
    float nrm = sqrtf(red[0]+red[1]+red[2]+red[3]);
    float u = v / nrm;
    size_t o = (size_t)row*DKD + d;
    fp16 hi, lo;
    split2(u, hi, lo); g_uhi[o] = hi; g_ulo[o] = lo;
    split2(v, hi, lo); g_hhi[o] = hi; g_hlo[o] = lo;
    if (d == 0) g_nrm[row] = nrm;
}

// ---------------- merge heads + norms + splits (between layers) ---------------
__global__ void k_mergenorm(const float* __restrict__ mb, int l)
{
    int row = blockIdx.x;
    int d = threadIdx.x;
    size_t o = (size_t)row*DKD + d;
    float a = mb[l];
#pragma unroll
    for (int h = 0; h < HH; h++) a += g_hs[(size_t)h*BSD + o];
    float sq = a*a;
#pragma unroll
    for (int of = 16; of; of >>= 1) sq += __shfl_xor_sync(0xffffffffu, sq, of);
    __shared__ float red[4];
    if ((d & 31) == 0) red[d>>5] = sq;
    __syncthreads();
    float nrm = sqrtf(red[0]+red[1]+red[2]+red[3]);
    g_h[o] = a;
    fp16 hi, lo;
    split2(a/nrm, hi, lo); g_uhi[o] = hi; g_ulo[o] = lo;
    split2(a,     hi, lo); g_hhi[o] = hi; g_hlo[o] = lo;
    if (d == 0) g_nrm[row] = nrm;
}

// ---------------- fused layer kernel ------------------------------------------
#define TSTRIDE 136
#define TILE1   (128*TSTRIDE*2)        /* 34816 bytes, one fp16 tile */
#define RPAIR   (2*TILE1)              /* hi+lo pair */
#define RAO     0                      /* pair: u -> P            */
#define RBO     RPAIR                  /* pair: T1 -> h           */
#define RCO     (2*RPAIR)              /* single: W -> Vw -> V^T  */
#define SMO_F   (2*RPAIR + TILE1)
#define SMEM_TOTAL (2*RPAIR + TILE1 + 6144)

__device__ __forceinline__ void load_pair_async(uint32_t dst,
    const fp16* __restrict__ hi, const fp16* __restrict__ lo, int tid)
{
#pragma unroll
    for (int it = 0; it < 8; it++) {
        int idx = it*256 + tid;
        int row = idx >> 4, chunk = idx & 15;
        uint32_t so = dst + (row*TSTRIDE + chunk*8)*2;
        CP16(so,         hi + row*DKD + chunk*8);
        CP16(so + TILE1, lo + row*DKD + chunk*8);
    }
}
__device__ __forceinline__ void load_hi_async(uint32_t dst,
    const fp16* __restrict__ hi, int tid)
{
#pragma unroll
    for (int it = 0; it < 4; it++) {
        int idx = it*256 + tid;          // 1024 chunks of 16B, 2 per iter... (8 halves)
        int row = idx >> 3, chunk = idx & 7;
        CP16(dst + (row*TSTRIDE + chunk*16)*2, hi + row*DKD + chunk*16);
        CP16(dst + (row*TSTRIDE + chunk*16 + 8)*2, hi + row*DKD + chunk*16 + 8);
    }
}

// 2-term (Ahi*Bhi + Alo*Bhi) 128x128x128 gemm; A = pair tile, B = hi tile
__device__ __forceinline__ void gemm2t(uint32_t aBase, uint32_t bBase,
                                       float acc[4][4][4], int lane, int wm, int wn)
{
    uint32_t aoff[4], b4off[2];
#pragma unroll
    for (int mi = 0; mi < 4; mi++)
        aoff[mi] = aBase + ((wm*64 + mi*16 + (lane & 15))*TSTRIDE + (lane >> 4)*8) * 2;
#pragma unroll
    for (int njp = 0; njp < 2; njp++)
        b4off[njp] = bBase + ((wn*32 + njp*16 + ((lane>>4)*8) + (lane & 7))*TSTRIDE
                              + (((lane >> 3) & 1)*8)) * 2;
#pragma unroll
    for (int mi = 0; mi < 4; mi++)
#pragma unroll
        for (int nj = 0; nj < 4; nj++)
#pragma unroll
            for (int q = 0; q < 4; q++) acc[mi][nj][q] = 0.0f;

#pragma unroll 2
    for (int kk = 0; kk < 8; kk++) {
        uint32_t k2 = kk*32;
        uint32_t ah[4][4], al[4][4], bh[2][4];
#pragma unroll
        for (int mi = 0; mi < 4; mi++) {
            ldmx4(ah[mi], aoff[mi] + k2);
            ldmx4(al[mi], aoff[mi] + TILE1 + k2);
        }
#pragma unroll
        for (int njp = 0; njp < 2; njp++)
            ldmx4(bh[njp], b4off[njp] + k2);
#pragma unroll
        for (int mi = 0; mi < 4; mi++)
#pragma unroll
            for (int nj = 0; nj < 4; nj++) {
                const uint32_t* bhp = &bh[nj>>1][(nj&1)*2];
                mma16816(acc[mi][nj], ah[mi], bhp);
                mma16816(acc[mi][nj], al[mi], bhp);
            }
    }
}

// accumulator fragments -> smem fp16 hi/lo pair tile (row-major A layout)
__device__ __forceinline__ void fragToTile(char* sm, uint32_t rOff, float acc[4][4][4],
                                           int lane, int wm, int wn)
{
    int gid = lane >> 2, tig = lane & 3;
#pragma unroll
    for (int mi = 0; mi < 4; mi++) {
        int r0 = wm*64 + mi*16 + gid;
#pragma unroll
        for (int nj = 0; nj < 4; nj++) {
            int c0 = wn*32 + nj*8 + tig*2;
#pragma unroll
            for (int half = 0; half < 2; half++) {
                int r = r0 + half*8;
                uint32_t hi, lo;
                split_pack2(acc[mi][nj][half*2], acc[mi][nj][half*2+1], hi, lo);
                *(uint32_t*)(sm + rOff + (r*TSTRIDE + c0)*2)         = hi;
                *(uint32_t*)(sm + rOff + TILE1 + (r*TSTRIDE + c0)*2) = lo;
            }
        }
    }
}

__global__ void __launch_bounds__(256, 1) k_layer(int l,
    const float* __restrict__ Vb, const float* __restrict__ lng,
    const float* __restrict__ lnb, const float* __restrict__ mw)
{
    extern __shared__ char sm[];
    uint32_t smb = smem_u32(sm);

    int bx = blockIdx.x;                 // batch / m-tile
    int h  = blockIdx.y;
    int tid = threadIdx.x, lane = tid & 31, wid = tid >> 5;
    int wm = wid >> 2, wn = wid & 3;
    int gid = lane >> 2, tig = lane & 3;

    float* fnrm = (float*)(sm + SMO_F);
    float* fvb  = fnrm + 128;
    float* fg   = fnrm + 256;
    float* fb   = fnrm + 384;
    float* red1 = fnrm + 512;            // 512 floats
    float* red2 = fnrm + 1024;           // 512 floats

    size_t tokBase = (size_t)bx*128*DKD;
    size_t lhOff   = (size_t)(l*HH + h)*DKD*DKD;
    size_t hsBase  = (size_t)h*BSD + tokBase;

    // group0: u pair -> RA, W hi -> RC
    load_pair_async(smb + RAO, g_uhi + tokBase, g_ulo + tokBase, tid);
    load_hi_async(smb + RCO, g_Wthi + lhOff, tid);
    CP_COMMIT();
    if (tid < 128) {
        fnrm[tid] = g_nrm[bx*128 + tid];
        fvb[tid]  = Vb[(l*HH+h)*DKD + tid];
        fg[tid]   = lng[(size_t)(l*HH+h)*DKD + tid];
        fb[tid]   = lnb[(size_t)(l*HH+h)*DKD + tid];
    }
    CP_WAIT0();
    __syncthreads();                       // S1

    float acc[4][4][4];

    // GEMM1: T1 = u @ W
    gemm2t(smb + RAO, smb + RCO, acc, lane, wm, wn);
    __syncthreads();                       // S2: RC (W) free for Vw
    fragToTile(sm, RBO, acc, lane, wm, wn);

    // Vw streams in under GEMM2
    load_hi_async(smb + RCO, g_Vwhi + lhOff, tid);
    CP_COMMIT();
    __syncthreads();                       // S3: T1 visible

    // GEMM2: M = T1 @ u^T  (B = u hi)
    gemm2t(smb + RBO, smb + RAO, acc, lane, wm, wn);
    __syncthreads();                       // S4: RB (T1) + RA (u) consumed

    // h streams in under softmax
    load_pair_async(smb + RBO, g_hhi + tokBase, g_hlo + tokBase, tid);
    CP_COMMIT();

    // ---- register softmax (A = M^2*n*n*scale >= 0, no max pass) ----
    {
        const float scale = 0.08838834764831845f;    // 1/sqrt(128)
        float nc[8];
#pragma unroll
        for (int nj = 0; nj < 4; nj++) {
            int c0 = wn*32 + nj*8 + tig*2;
            nc[2*nj]   = fnrm[c0];
            nc[2*nj+1] = fnrm[c0+1];
        }
#pragma unroll
        for (int mi = 0; mi < 4; mi++)
#pragma unroll
        for (int half = 0; half < 2; half++) {
            int r = wm*64 + mi*16 + half*8 + gid;
            float nr = fnrm[r] * scale;
            float s = 0.0f;
#pragma unroll
            for (int nj = 0; nj < 4; nj++) {
                float m0 = acc[mi][nj][half*2], m1 = acc[mi][nj][half*2+1];
                float e0 = __expf(m0*m0 * nr * nc[2*nj]);
                float e1 = __expf(m1*m1 * nr * nc[2*nj+1]);
                acc[mi][nj][half*2]   = e0;
                acc[mi][nj][half*2+1] = e1;
                s += e0 + e1;
            }
            s += __shfl_xor_sync(0xffffffffu, s, 1);
            s += __shfl_xor_sync(0xffffffffu, s, 2);
            if (tig == 0) red1[r*4 + wn] = s;
        }
        __syncthreads();                   // S5: row partial sums
#pragma unroll
        for (int mi = 0; mi < 4; mi++)
#pragma unroll
        for (int half = 0; half < 2; half++) {
            int r = wm*64 + mi*16 + half*8 + gid;
            float inv = 1.0f / (red1[r*4] + red1[r*4+1] + red1[r*4+2] + red1[r*4+3]);
#pragma unroll
            for (int nj = 0; nj < 4; nj++) {
                int c0 = wn*32 + nj*8 + tig*2;
                uint32_t hi, lo;
                split_pack2(acc[mi][nj][half*2]*inv, acc[mi][nj][half*2+1]*inv, hi, lo);
                *(uint32_t*)(sm + RAO + (r*TSTRIDE + c0)*2)         = hi;
                *(uint32_t*)(sm + RAO + TILE1 + (r*TSTRIDE + c0)*2) = lo;
            }
        }
    }
    CP_WAIT0();
    __syncthreads();                       // S6: P visible, h + Vw loaded

    // GEMM3: V = h @ Vw^T
    gemm2t(smb + RBO, smb + RCO, acc, lane, wm, wn);
    __syncthreads();                       // S7: RC (Vw) consumed

    // V^T + bias -> RC (hi only)
#pragma unroll
    for (int mi = 0; mi < 4; mi++) {
        int s0 = wm*64 + mi*16 + gid;
#pragma unroll
        for (int nj = 0; nj < 4; nj++) {
            int e0 = wn*32 + nj*8 + tig*2;
            float vb0 = fvb[e0], vb1 = fvb[e0+1];
#pragma unroll
            for (int half = 0; half < 2; half++) {
                int ss = s0 + half*8;
                *(fp16*)(sm + RCO + (e0*TSTRIDE + ss)*2)     = __float2half_rn(acc[mi][nj][half*2]   + vb0);
                *(fp16*)(sm + RCO + ((e0+1)*TSTRIDE + ss)*2) = __float2half_rn(acc[mi][nj][half*2+1] + vb1);
            }
        }
    }
    __syncthreads();                       // S8: V^T staged

    // GEMM4: O = P @ V^T
    gemm2t(smb + RAO, smb + RCO, acc, lane, wm, wn);

    // ---- register epilogue: +residual, LN (E[x^2]-m^2), *mw -> g_hs ----
    {
        float gg[8], bb[8];
#pragma unroll
        for (int nj = 0; nj < 4; nj++) {
            int c0 = wn*32 + nj*8 + tig*2;
            gg[2*nj] = fg[c0]; gg[2*nj+1] = fg[c0+1];
            bb[2*nj] = fb[c0]; bb[2*nj+1] = fb[c0+1];
        }
        float mwv = __ldg(mw + l*HH + h);
#pragma unroll
        for (int mi = 0; mi < 4; mi++)
#pragma unroll
        for (int half = 0; half < 2; half++) {
            int r = wm*64 + mi*16 + half*8 + gid;
            const float* hr = g_h + tokBase + (size_t)r*DKD;
            float s = 0.0f, s2 = 0.0f;
#pragma unroll
            for (int nj = 0; nj < 4; nj++) {
                int c0 = wn*32 + nj*8 + tig*2;
                float2 rv = *(const float2*)(hr + c0);
                float v0 = acc[mi][nj][half*2]   + rv.x;
                float v1 = acc[mi][nj][half*2+1] + rv.y;
                acc[mi][nj][half*2]   = v0;
                acc[mi][nj][half*2+1] = v1;
                s  += v0 + v1;
                s2 += v0*v0 + v1*v1;
            }
            s  += __shfl_xor_sync(0xffffffffu, s, 1);
            s  += __shfl_xor_sync(0xffffffffu, s, 2);
            s2 += __shfl_xor_sync(0xffffffffu, s2, 1);
            s2 += __shfl_xor_sync(0xffffffffu, s2, 2);
            if (tig == 0) { red1[r*4 + wn] = s; red2[r*4 + wn] = s2; }
        }
        __syncthreads();                   // S9
#pragma unroll
        for (int mi = 0; mi < 4; mi++)
#pragma unroll
        for (int half = 0; half < 2; half++) {
            int r = wm*64 + mi*16 + half*8 + gid;
            float s  = red1[r*4] + red1[r*4+1] + red1[r*4+2] + red1[r*4+3];
            float s2 = red2[r*4] + red2[r*4+1] + red2[r*4+2] + red2[r*4+3];
            float mean = s * (1.0f/DKD);
            float var  = s2 * (1.0f/DKD) - mean*mean;
            float inv  = rsqrtf(var + 1e-5f);
            float* op = g_hs + hsBase + (size_t)r*DKD;
#pragma unroll
            for (int nj = 0; nj < 4; nj++) {
                int c0 = wn*32 + nj*8 + tig*2;
                float2 o;
                o.x = ((acc[mi][nj][half*2]  -mean)*inv*gg[2*nj]   + bb[2*nj]  ) * mwv;
                o.y = ((acc[mi][nj][half*2+1]-mean)*inv*gg[2*nj+1] + bb[2*nj+1]) * mwv;
                *(float2*)(op + c0) = o;
            }
        }
    }
}

// ---------------- extract last token ------------------------------------------
__global__ void k_extract(float* __restrict__ out)
{
    int i = blockIdx.x*blockDim.x + threadIdx.x;
    if (i < BATCH*DKD) {
        int b = i >> 7, d = i & 127;
        out[i] = g_h[((size_t)b*SS + (SS-1))*DKD + d];
    }
}

// ---------------- launch ------------------------------------------------------
extern "C" void kernel_launch(void* const* d_in, const int* in_sizes, int n_in,
                              void* d_out, int out_size)
{
    const float* x        = (const float*)d_in[0];
    const float* embed_w  = (const float*)d_in[1];
    const float* embed_b  = (const float*)d_in[2];
    const float* class_tk = (const float*)d_in[3];
    const float* norm0_g  = (const float*)d_in[4];
    const float* norm0_b  = (const float*)d_in[5];
    const float* Vw       = (const float*)d_in[6];
    const float* Vb       = (const float*)d_in[7];
    const float* ln_g     = (const float*)d_in[8];
    const float* ln_b     = (const float*)d_in[9];
    const float* phi      = (const float*)d_in[10];
    const float* merger_w = (const float*)d_in[11];
    const float* merger_b = (const float*)d_in[12];
    float* out = (float*)d_out;

    static int smem_set = 0;
    if (!smem_set) {
        cudaFuncSetAttribute(k_layer, cudaFuncAttributeMaxDynamicSharedMemorySize, SMEM_TOTAL);
        smem_set = 1;
    }

    k_embed<<<BS, 128>>>(x, embed_w, embed_b, class_tk, norm0_g, norm0_b);
    k_cs<<<(LHN*PP + 255)/256, 256>>>(phi);
    k_wbuild<<<dim3(LHN, 4), 256>>>();
    k_cvtVw<<<(LHN*DKD*DKD + 255)/256, 256>>>(Vw);
    k_norm<<<BS, 128>>>();

    dim3 gg(BATCH, HH);
    for (int l = 0; l < LL; l++) {
        k_layer<<<gg, 256, SMEM_TOTAL>>>(l, Vb, ln_g, ln_b, merger_w);
        k_mergenorm<<<BS, 128>>>(merger_b, l);
    }
    k_extract<<<(BATCH*DKD + 255)/256, 256>>>(out);
}

// round 10
// speedup vs baseline: 1.8179x; 1.0342x over previous
#include <cuda_runtime.h>
#include <cuda_fp16.h>
#include <cstdint>
#include <math.h>

#define BATCH 128
#define TT    127
#define SS    128
#define DIN   48
#define DKD   128
#define HH    8
#define LL    6
#define PP    8128
#define LHN   48
#define BS    (BATCH*SS)     /* 16384 */
#define BSD   (BS*DKD)       /* 2097152 */

typedef __half fp16;

// ---------------- scratch ----------------------------------------------------
__device__ float g_h[BSD];
__device__ float g_nrm[BS];
__device__ float g_cosv[LHN*PP];
__device__ float g_sinv[LHN*PP];
__device__ fp16  g_uhi[BSD],  g_ulo[BSD];
__device__ fp16  g_Wthi[LHN*DKD*DKD];            /* B-side: hi only */
__device__ fp16  g_Vwhi[LHN*DKD*DKD];            /* B-side: hi only */
__device__ float g_hs[(size_t)HH*BSD];

// ---------------- helpers -----------------------------------------------------
__device__ __forceinline__ uint32_t smem_u32(const void* p) {
    uint32_t a;
    asm("{ .reg .u64 t; cvta.to.shared.u64 t, %1; cvt.u32.u64 %0, t; }" : "=r"(a) : "l"(p));
    return a;
}
__device__ __forceinline__ void split2(float x, fp16& h, fp16& l)
{
    h = __float2half_rn(x);
    l = __float2half_rn(x - __half2float(h));
}
__device__ __forceinline__ void split_pack2(float x, float y, uint32_t& hi, uint32_t& lo)
{
    fp16 hx, lx, hy, ly;
    split2(x, hx, lx); split2(y, hy, ly);
    __half2 H = __halves2half2(hx, hy);
    __half2 L = __halves2half2(lx, ly);
    hi = *reinterpret_cast<uint32_t*>(&H);
    lo = *reinterpret_cast<uint32_t*>(&L);
}
__device__ __forceinline__ void ldmx4(uint32_t* r, uint32_t addr)
{
    asm volatile("ldmatrix.sync.aligned.m8n8.x4.shared.b16 {%0,%1,%2,%3}, [%4];"
        : "=r"(r[0]), "=r"(r[1]), "=r"(r[2]), "=r"(r[3]) : "r"(addr));
}
__device__ __forceinline__ void mma16816(float* d, const uint32_t* a, const uint32_t* b)
{
    asm volatile("mma.sync.aligned.m16n8k16.row.col.f32.f16.f16.f32 "
        "{%0,%1,%2,%3}, {%4,%5,%6,%7}, {%8,%9}, {%0,%1,%2,%3};"
        : "+f"(d[0]), "+f"(d[1]), "+f"(d[2]), "+f"(d[3])
        : "r"(a[0]), "r"(a[1]), "r"(a[2]), "r"(a[3]), "r"(b[0]), "r"(b[1]));
}
#define CP16(dst, src) \
    asm volatile("cp.async.cg.shared.global [%0], [%1], 16;" :: "r"(dst), "l"(src))
#define CP_COMMIT() asm volatile("cp.async.commit_group;" ::: "memory")
#define CP_WAIT0()  asm volatile("cp.async.wait_group 0;" ::: "memory")
#define CP_WAIT1()  asm volatile("cp.async.wait_group 1;" ::: "memory")

// ---------------- embed + class token + LN0 ---------------------------------
__global__ void k_embed(const float* __restrict__ x, const float* __restrict__ ew,
                        const float* __restrict__ eb, const float* __restrict__ ct,
                        const float* __restrict__ g0, const float* __restrict__ b0)
{
    int bx = blockIdx.x;
    int b = bx >> 7, s = bx & 127;
    int d = threadIdx.x;
    __shared__ float xs[DIN];
    __shared__ float red[8];
    float v;
    if (s == 0) {
        v = ct[d];
    } else {
        if (d < DIN) xs[d] = x[(b*TT + (s-1))*DIN + d];
        __syncthreads();
        float acc = eb[d];
        const float* wrow = ew + d*DIN;
#pragma unroll
        for (int f = 0; f < DIN; f++) acc += xs[f]*wrow[f];
        v = acc;
    }
    float sum = v, sq = v*v;
#pragma unroll
    for (int o = 16; o; o >>= 1) {
        sum += __shfl_xor_sync(0xffffffffu, sum, o);
        sq  += __shfl_xor_sync(0xffffffffu, sq,  o);
    }
    if ((d & 31) == 0) { red[d>>5] = sum; red[4 + (d>>5)] = sq; }
    __syncthreads();
    float ts = red[0]+red[1]+red[2]+red[3];
    float tq = red[4]+red[5]+red[6]+red[7];
    float mean = ts * (1.0f/DKD);
    float var  = tq * (1.0f/DKD) - mean*mean;
    float inv  = rsqrtf(var + 1e-5f);
    g_h[(size_t)bx*DKD + d] = (v - mean)*inv*g0[d] + b0[d];
}

// ---------------- sincos precompute ------------------------------------------
__global__ void k_cs(const float* __restrict__ phi)
{
    int i = blockIdx.x*blockDim.x + threadIdx.x;
    if (i < LHN*PP) {
        float s, c;
        sincosf(phi[i], &s, &c);
        g_cosv[i] = c; g_sinv[i] = s;
    }
}

// ---------------- convert Vw (hi only) ----------------------------------------
__global__ void k_cvtVw(const float* __restrict__ Vw)
{
    int i = blockIdx.x*blockDim.x + threadIdx.x;
    if (i < LHN*DKD*DKD) g_Vwhi[i] = __float2half_rn(Vw[i]);
}

// ---------------- W build: brick-wall Givens pyramid -> transposed hi ---------
__global__ __launch_bounds__(256) void k_wbuild()
{
    int lh = blockIdx.x, cg = blockIdx.y;      // 48 x 4
    __shared__ float Wsh[SS][33];
    int tid = threadIdx.x;
    int col = tid & 31, slot = tid >> 5;
    for (int idx = tid; idx < SS*32; idx += 256) {
        int r = idx >> 5, c = idx & 31;
        Wsh[r][c] = (r == cg*32 + c) ? 1.0f : 0.0f;
    }
    __syncthreads();
    const float* cb = g_cosv + lh*PP;
    const float* sb = g_sinv + lh*PP;
    for (int t = 0; t <= 2*(SS-2); t++) {
        int par  = t & 1;
        int imax = min(t, 2*(SS-2) - t);
        int cnt  = ((imax - par) >> 1) + 1;
        for (int r = slot; r < cnt; r += 8) {
            int i = par + 2*r;
            int k = (t + i) >> 1;
            int p = ((k*(k+1)) >> 1) + k - i;
            float c = cb[p], s = sb[p];
            float ra = Wsh[i][col], rb = Wsh[i+1][col];
            Wsh[i][col]   = c*ra - s*rb;
            Wsh[i+1][col] = s*ra + c*rb;
        }
        __syncthreads();
    }
    for (int idx = tid; idx < 32*SS; idx += 256) {
        int r = idx & 127, c = idx >> 7;
        size_t o = (size_t)lh*DKD*DKD + (size_t)(cg*32 + c)*DKD + r;
        g_Wthi[o] = __float2half_rn(Wsh[r][c]);
    }
}

// ---------------- token norms + u splits (layer-0 prep) -----------------------
__global__ void k_norm()
{
    int row = blockIdx.x;
    int d = threadIdx.x;
    float v = g_h[(size_t)row*DKD + d];
    float sq = v*v;
#pragma unroll
    for (int o = 16; o; o >>= 1) sq += __shfl_xor_sync(0xffffffffu, sq, o);
    __shared__ float red[4];
    if ((d & 31) == 0) red[d>>5] = sq;
    __syncthreads();
    float nrm = sqrtf(red[0]+red[1]+red[2]+red[3]);
    float u = v / nrm;
    size_t o = (size_t)row*DKD + d;
    fp16 hi, lo;
    split2(u, hi, lo); g_uhi[o] = hi; g_ulo[o] = lo;
    if (d == 0) g_nrm[row] = nrm;
}

// ---------------- merge heads + norms + u splits (between layers) -------------
__global__ void k_mergenorm(const float* __restrict__ mb, int l)
{
    int row = blockIdx.x;
    int d = threadIdx.x;
    size_t o = (size_t)row*DKD + d;
    float a = mb[l];
#pragma unroll
    for (int h = 0; h < HH; h++) a += g_hs[(size_t)h*BSD + o];
    float sq = a*a;
#pragma unroll
    for (int of = 16; of; of >>= 1) sq += __shfl_xor_sync(0xffffffffu, sq, of);
    __shared__ float red[4];
    if ((d & 31) == 0) red[d>>5] = sq;
    __syncthreads();
    float nrm = sqrtf(red[0]+red[1]+red[2]+red[3]);
    g_h[o] = a;
    fp16 hi, lo;
    split2(a/nrm, hi, lo); g_uhi[o] = hi; g_ulo[o] = lo;
    if (d == 0) g_nrm[row] = nrm;
}

// ---------------- fused layer kernel ------------------------------------------
#define TSTRIDE 136
#define TILE1   (128*TSTRIDE*2)        /* 34816 bytes, one fp16 tile */
#define RPAIR   (2*TILE1)              /* hi+lo pair */
#define RAO     0                      /* pair: u (persistent thru GEMM3) */
#define RBO     RPAIR                  /* pair: T1 -> P                   */
#define RCO     (2*RPAIR)              /* single: W -> V^T                */
#define RDO     (2*RPAIR + TILE1)      /* single: Vw                      */
#define SMO_F   (2*RPAIR + 2*TILE1)
#define SMEM_TOTAL (2*RPAIR + 2*TILE1 + 6144)

__device__ __forceinline__ void load_pair_async(uint32_t dst,
    const fp16* __restrict__ hi, const fp16* __restrict__ lo, int tid)
{
#pragma unroll
    for (int it = 0; it < 8; it++) {
        int idx = it*256 + tid;
        int row = idx >> 4, chunk = idx & 15;
        uint32_t so = dst + (row*TSTRIDE + chunk*8)*2;
        CP16(so,         hi + row*DKD + chunk*8);
        CP16(so + TILE1, lo + row*DKD + chunk*8);
    }
}
__device__ __forceinline__ void load_hi_async(uint32_t dst,
    const fp16* __restrict__ hi, int tid)
{
#pragma unroll
    for (int it = 0; it < 4; it++) {
        int idx = it*256 + tid;
        int row = idx >> 3, chunk = idx & 7;
        CP16(dst + (row*TSTRIDE + chunk*16)*2, hi + row*DKD + chunk*16);
        CP16(dst + (row*TSTRIDE + chunk*16 + 8)*2, hi + row*DKD + chunk*16 + 8);
    }
}

// 2-term (Ahi*Bhi + Alo*Bhi) 128x128x128 gemm; A = pair tile, B = hi tile
__device__ __forceinline__ void gemm2t(uint32_t aBase, uint32_t bBase,
                                       float acc[4][4][4], int lane, int wm, int wn)
{
    uint32_t aoff[4], b4off[2];
#pragma unroll
    for (int mi = 0; mi < 4; mi++)
        aoff[mi] = aBase + ((wm*64 + mi*16 + (lane & 15))*TSTRIDE + (lane >> 4)*8) * 2;
#pragma unroll
    for (int njp = 0; njp < 2; njp++)
        b4off[njp] = bBase + ((wn*32 + njp*16 + ((lane>>4)*8) + (lane & 7))*TSTRIDE
                              + (((lane >> 3) & 1)*8)) * 2;
#pragma unroll
    for (int mi = 0; mi < 4; mi++)
#pragma unroll
        for (int nj = 0; nj < 4; nj++)
#pragma unroll
            for (int q = 0; q < 4; q++) acc[mi][nj][q] = 0.0f;

#pragma unroll 2
    for (int kk = 0; kk < 8; kk++) {
        uint32_t k2 = kk*32;
        uint32_t ah[4][4], al[4][4], bh[2][4];
#pragma unroll
        for (int mi = 0; mi < 4; mi++) {
            ldmx4(ah[mi], aoff[mi] + k2);
            ldmx4(al[mi], aoff[mi] + TILE1 + k2);
        }
#pragma unroll
        for (int njp = 0; njp < 2; njp++)
            ldmx4(bh[njp], b4off[njp] + k2);
#pragma unroll
        for (int mi = 0; mi < 4; mi++)
#pragma unroll
            for (int nj = 0; nj < 4; nj++) {
                const uint32_t* bhp = &bh[nj>>1][(nj&1)*2];
                mma16816(acc[mi][nj], ah[mi], bhp);
                mma16816(acc[mi][nj], al[mi], bhp);
            }
    }
}

// accumulator fragments -> smem fp16 hi/lo pair tile (row-major A layout)
__device__ __forceinline__ void fragToTile(char* sm, uint32_t rOff, float acc[4][4][4],
                                           int lane, int wm, int wn)
{
    int gid = lane >> 2, tig = lane & 3;
#pragma unroll
    for (int mi = 0; mi < 4; mi++) {
        int r0 = wm*64 + mi*16 + gid;
#pragma unroll
        for (int nj = 0; nj < 4; nj++) {
            int c0 = wn*32 + nj*8 + tig*2;
#pragma unroll
            for (int half = 0; half < 2; half++) {
                int r = r0 + half*8;
                uint32_t hi, lo;
                split_pack2(acc[mi][nj][half*2], acc[mi][nj][half*2+1], hi, lo);
                *(uint32_t*)(sm + rOff + (r*TSTRIDE + c0)*2)         = hi;
                *(uint32_t*)(sm + rOff + TILE1 + (r*TSTRIDE + c0)*2) = lo;
            }
        }
    }
}

__global__ void __launch_bounds__(256, 1) k_layer(int l,
    const float* __restrict__ Vb, const float* __restrict__ lng,
    const float* __restrict__ lnb, const float* __restrict__ mw)
{
    extern __shared__ char sm[];
    uint32_t smb = smem_u32(sm);

    int bx = blockIdx.x;                 // batch / m-tile
    int h  = blockIdx.y;
    int tid = threadIdx.x, lane = tid & 31, wid = tid >> 5;
    int wm = wid >> 2, wn = wid & 3;
    int gid = lane >> 2, tig = lane & 3;

    float* fnrm = (float*)(sm + SMO_F);
    float* fvb  = fnrm + 128;
    float* fg   = fnrm + 256;
    float* fb   = fnrm + 384;
    float* red1 = fnrm + 512;            // 512 floats
    float* red2 = fnrm + 1024;           // 512 floats

    size_t tokBase = (size_t)bx*128*DKD;
    size_t lhOff   = (size_t)(l*HH + h)*DKD*DKD;
    size_t hsBase  = (size_t)h*BSD + tokBase;

    // group0: u pair -> RA, W hi -> RC ; group1: Vw hi -> RD
    load_pair_async(smb + RAO, g_uhi + tokBase, g_ulo + tokBase, tid);
    load_hi_async(smb + RCO, g_Wthi + lhOff, tid);
    CP_COMMIT();
    load_hi_async(smb + RDO, g_Vwhi + lhOff, tid);
    CP_COMMIT();
    if (tid < 128) {
        fnrm[tid] = g_nrm[bx*128 + tid];
        fvb[tid]  = Vb[(l*HH+h)*DKD + tid];
        fg[tid]   = lng[(size_t)(l*HH+h)*DKD + tid];
        fb[tid]   = lnb[(size_t)(l*HH+h)*DKD + tid];
    }
    CP_WAIT1();                            // u + W landed (Vw may still fly)
    __syncthreads();                       // S1

    float acc[4][4][4];

    // GEMM1: T1 = u @ W  (A=RA pair, B=RC)
    gemm2t(smb + RAO, smb + RCO, acc, lane, wm, wn);
    fragToTile(sm, RBO, acc, lane, wm, wn);   // RB had no prior readers
    __syncthreads();                       // S2: T1 visible, RC free

    // GEMM2: M = T1 @ u^T  (A=RB pair, B=RA hi)
    gemm2t(smb + RBO, smb + RAO, acc, lane, wm, wn);
    CP_WAIT0();                            // Vw landed (this thread's parts)
    __syncthreads();                       // S3: RB free; Vw visible to all

    // ---- register softmax (A = M^2*n*n*scale >= 0, no max pass) ----
    {
        const float scale = 0.08838834764831845f;    // 1/sqrt(128)
        float nc[8];
#pragma unroll
        for (int nj = 0; nj < 4; nj++) {
            int c0 = wn*32 + nj*8 + tig*2;
            nc[2*nj]   = fnrm[c0];
            nc[2*nj+1] = fnrm[c0+1];
        }
#pragma unroll
        for (int mi = 0; mi < 4; mi++)
#pragma unroll
        for (int half = 0; half < 2; half++) {
            int r = wm*64 + mi*16 + half*8 + gid;
            float nr = fnrm[r] * scale;
            float s = 0.0f;
#pragma unroll
            for (int nj = 0; nj < 4; nj++) {
                float m0 = acc[mi][nj][half*2], m1 = acc[mi][nj][half*2+1];
                float e0 = __expf(m0*m0 * nr * nc[2*nj]);
                float e1 = __expf(m1*m1 * nr * nc[2*nj+1]);
                acc[mi][nj][half*2]   = e0;
                acc[mi][nj][half*2+1] = e1;
                s += e0 + e1;
            }
            s += __shfl_xor_sync(0xffffffffu, s, 1);
            s += __shfl_xor_sync(0xffffffffu, s, 2);
            if (tig == 0) red1[r*4 + wn] = s;
        }
        __syncthreads();                   // S4: row partial sums
#pragma unroll
        for (int mi = 0; mi < 4; mi++)
#pragma unroll
        for (int half = 0; half < 2; half++) {
            int r = wm*64 + mi*16 + half*8 + gid;
            float inv = 1.0f / (red1[r*4] + red1[r*4+1] + red1[r*4+2] + red1[r*4+3]);
#pragma unroll
            for (int nj = 0; nj < 4; nj++) {
                int c0 = wn*32 + nj*8 + tig*2;
                uint32_t hi, lo;
                split_pack2(acc[mi][nj][half*2]*inv, acc[mi][nj][half*2+1]*inv, hi, lo);
                *(uint32_t*)(sm + RBO + (r*TSTRIDE + c0)*2)         = hi;
                *(uint32_t*)(sm + RBO + TILE1 + (r*TSTRIDE + c0)*2) = lo;
            }
        }
    }

    // GEMM3: V' = u @ Vw^T  (A=RA pair, B=RD) ; V = nrm[t]*V' + vb[e]
    gemm2t(smb + RAO, smb + RDO, acc, lane, wm, wn);

    // V^T -> RC (hi only), scale by nrm, add bias
#pragma unroll
    for (int mi = 0; mi < 4; mi++) {
        int s0 = wm*64 + mi*16 + gid;
#pragma unroll
        for (int nj = 0; nj < 4; nj++) {
            int e0 = wn*32 + nj*8 + tig*2;
            float vb0 = fvb[e0], vb1 = fvb[e0+1];
#pragma unroll
            for (int half = 0; half < 2; half++) {
                int ss = s0 + half*8;
                float ns = fnrm[ss];
                *(fp16*)(sm + RCO + (e0*TSTRIDE + ss)*2)     = __float2half_rn(acc[mi][nj][half*2]*ns   + vb0);
                *(fp16*)(sm + RCO + ((e0+1)*TSTRIDE + ss)*2) = __float2half_rn(acc[mi][nj][half*2+1]*ns + vb1);
            }
        }
    }
    __syncthreads();                       // S5: P (RB) + V^T (RC) staged

    // GEMM4: O = P @ V^T  (A=RB pair, B=RC)
    gemm2t(smb + RBO, smb + RCO, acc, lane, wm, wn);

    // ---- register epilogue: +residual, LN (E[x^2]-m^2), *mw -> g_hs ----
    {
        float gg[8], bb[8];
#pragma unroll
        for (int nj = 0; nj < 4; nj++) {
            int c0 = wn*32 + nj*8 + tig*2;
            gg[2*nj] = fg[c0]; gg[2*nj+1] = fg[c0+1];
            bb[2*nj] = fb[c0]; bb[2*nj+1] = fb[c0+1];
        }
        float mwv = __ldg(mw + l*HH + h);
#pragma unroll
        for (int mi = 0; mi < 4; mi++)
#pragma unroll
        for (int half = 0; half < 2; half++) {
            int r = wm*64 + mi*16 + half*8 + gid;
            const float* hr = g_h + tokBase + (size_t)r*DKD;
            float s = 0.0f, s2 = 0.0f;
#pragma unroll
            for (int nj = 0; nj < 4; nj++) {
                int c0 = wn*32 + nj*8 + tig*2;
                float2 rv = *(const float2*)(hr + c0);
                float v0 = acc[mi][nj][half*2]   + rv.x;
                float v1 = acc[mi][nj][half*2+1] + rv.y;
                acc[mi][nj][half*2]   = v0;
                acc[mi][nj][half*2+1] = v1;
                s  += v0 + v1;
                s2 += v0*v0 + v1*v1;
            }
            s  += __shfl_xor_sync(0xffffffffu, s, 1);
            s  += __shfl_xor_sync(0xffffffffu, s, 2);
            s2 += __shfl_xor_sync(0xffffffffu, s2, 1);
            s2 += __shfl_xor_sync(0xffffffffu, s2, 2);
            if (tig == 0) { red1[r*4 + wn] = s; red2[r*4 + wn] = s2; }
        }
        __syncthreads();                   // S6
#pragma unroll
        for (int mi = 0; mi < 4; mi++)
#pragma unroll
        for (int half = 0; half < 2; half++) {
            int r = wm*64 + mi*16 + half*8 + gid;
            float s  = red1[r*4] + red1[r*4+1] + red1[r*4+2] + red1[r*4+3];
            float s2 = red2[r*4] + red2[r*4+1] + red2[r*4+2] + red2[r*4+3];
            float mean = s * (1.0f/DKD);
            float var  = s2 * (1.0f/DKD) - mean*mean;
            float inv  = rsqrtf(var + 1e-5f);
            float* op = g_hs + hsBase + (size_t)r*DKD;
#pragma unroll
            for (int nj = 0; nj < 4; nj++) {
                int c0 = wn*32 + nj*8 + tig*2;
                float2 o;
                o.x = ((acc[mi][nj][half*2]  -mean)*inv*gg[2*nj]   + bb[2*nj]  ) * mwv;
                o.y = ((acc[mi][nj][half*2+1]-mean)*inv*gg[2*nj+1] + bb[2*nj+1]) * mwv;
                *(float2*)(op + c0) = o;
            }
        }
    }
}

// ---------------- extract last token ------------------------------------------
__global__ void k_extract(float* __restrict__ out)
{
    int i = blockIdx.x*blockDim.x + threadIdx.x;
    if (i < BATCH*DKD) {
        int b = i >> 7, d = i & 127;
        out[i] = g_h[((size_t)b*SS + (SS-1))*DKD + d];
    }
}

// ---------------- launch ------------------------------------------------------
extern "C" void kernel_launch(void* const* d_in, const int* in_sizes, int n_in,
                              void* d_out, int out_size)
{
    const float* x        = (const float*)d_in[0];
    const float* embed_w  = (const float*)d_in[1];
    const float* embed_b  = (const float*)d_in[2];
    const float* class_tk = (const float*)d_in[3];
    const float* norm0_g  = (const float*)d_in[4];
    const float* norm0_b  = (const float*)d_in[5];
    const float* Vw       = (const float*)d_in[6];
    const float* Vb       = (const float*)d_in[7];
    const float* ln_g     = (const float*)d_in[8];
    const float* ln_b     = (const float*)d_in[9];
    const float* phi      = (const float*)d_in[10];
    const float* merger_w = (const float*)d_in[11];
    const float* merger_b = (const float*)d_in[12];
    float* out = (float*)d_out;

    static int smem_set = 0;
    if (!smem_set) {
        cudaFuncSetAttribute(k_layer, cudaFuncAttributeMaxDynamicSharedMemorySize, SMEM_TOTAL);
        smem_set = 1;
    }

    k_embed<<<BS, 128>>>(x, embed_w, embed_b, class_tk, norm0_g, norm0_b);
    k_cs<<<(LHN*PP + 255)/256, 256>>>(phi);
    k_wbuild<<<dim3(LHN, 4), 256>>>();
    k_cvtVw<<<(LHN*DKD*DKD + 255)/256, 256>>>(Vw);
    k_norm<<<BS, 128>>>();

    dim3 gg(BATCH, HH);
    for (int l = 0; l < LL; l++) {
        k_layer<<<gg, 256, SMEM_TOTAL>>>(l, Vb, ln_g, ln_b, merger_w);
        k_mergenorm<<<BS, 128>>>(merger_b, l);
    }
    k_extract<<<(BATCH*DKD + 255)/256, 256>>>(out);
}